// round 14
// baseline (speedup 1.0000x reference)
#include <cuda_runtime.h>
#include <cuda_fp16.h>
#include <cuda_bf16.h>
#include <math.h>
#include <stdint.h>

#define B_ 8
#define E_ 16384
#define O_ 256

// ---------------- scratch (__device__ globals; no allocs allowed) ----------------
__device__ float g_U [(size_t)B_*E_*128];   // from_up, edge-major
__device__ float g_X [(size_t)B_*E_*512];   // concat(conv1, from_down), edge-major
__device__ float g_Z [(size_t)B_*E_*256];   // Z1 (conv2 out), later Z3 (conv4 out)
__device__ float g_Z2[(size_t)B_*E_*256];   // Z2 (conv3 out)
__device__ float g_X2[(size_t)B_*E_*256];   // block-A output (residual input for final)
__device__ __half g_Wup [5*128*256];
__device__ __half g_W1r [5*512*256];
__device__ __half g_W2ar[5*256*256];
__device__ __half g_W2br[5*256*256];
// stats: [0]=sum1 [2048]=ssq1 [4096]=sum2 [6144]=ssq2 [8192]=sum3 [10240]=ssq3
__device__ float g_stats[6*2048];
__device__ float g_mean [B_*256];
__device__ float g_rstd [B_*256];
__device__ float g_mean2[B_*256];
__device__ float g_rstd2[B_*256];

__device__ __forceinline__ uint32_t smem_u32(const void* p) {
    uint32_t a;
    asm("{ .reg .u64 t; cvta.to.shared.u64 t, %1; cvt.u32.u64 %0, t; }" : "=r"(a) : "l"(p));
    return a;
}
#define CP_ASYNC16(dst, src) \
    asm volatile("cp.async.cg.shared.global [%0], [%1], 16;" :: "r"(dst), "l"(src))
#define CP_COMMIT() asm volatile("cp.async.commit_group;" ::: "memory")
#define CP_WAIT2()  asm volatile("cp.async.wait_group 2;" ::: "memory")
#define CP_WAIT0()  asm volatile("cp.async.wait_group 0;" ::: "memory")
#define BAR_SYNC_N(id, cnt)   asm volatile("bar.sync %0, %1;"   :: "r"(id), "r"(cnt) : "memory")
#define BAR_ARRIVE_N(id, cnt) asm volatile("bar.arrive %0, %1;" :: "r"(id), "r"(cnt) : "memory")
#define LDSM_X4(r0, r1, r2, r3, addr) \
    asm volatile("ldmatrix.sync.aligned.m8n8.x4.shared.b16 {%0,%1,%2,%3}, [%4];" \
        : "=r"(r0), "=r"(r1), "=r"(r2), "=r"(r3) : "r"(addr))

__device__ __forceinline__ void mma16816(float* d, const uint32_t* a, const uint32_t* b)
{
    asm volatile(
        "mma.sync.aligned.m16n8k16.row.col.f32.f16.f16.f32 "
        "{%0,%1,%2,%3}, {%4,%5,%6,%7}, {%8,%9}, {%0,%1,%2,%3};"
        : "+f"(d[0]), "+f"(d[1]), "+f"(d[2]), "+f"(d[3])
        : "r"(a[0]), "r"(a[1]), "r"(a[2]), "r"(a[3]), "r"(b[0]), "r"(b[1]));
}

__device__ __forceinline__ uint32_t h2u(float x, float y) {
    __half2 h = __floats2half2_rn(x, y);
    return *reinterpret_cast<uint32_t*>(&h);
}

// ---------------- slab map ----------------
// slab s (32 K-rows): cc = s/5, r = s%5
//  r=0: kind0 (center), channels [32cc, +32)
//  r=1: pair(1,3) chunk [32cc, +16)      rows 0-15 = n1+n3, rows 16-31 = |n1-n3|
//  r=2: pair(1,3) chunk [32cc+16, +16)
//  r=3: pair(2,4) chunk [32cc, +16)
//  r=4: pair(2,4) chunk [32cc+16, +16)

// ---------------- merged weight image prep ----------------
__global__ void prep_w_all(const float* __restrict__ W_up, const float* __restrict__ W1,
                           const float* __restrict__ W2a, const float* __restrict__ W2b,
                           __half* __restrict__ Wup, __half* __restrict__ W1r,
                           __half* __restrict__ W2ar, __half* __restrict__ W2br)
{
    int i = blockIdx.x * blockDim.x + threadIdx.x;   // < 180*8192
    int s = i >> 13;
    int within = i & 8191;
    const float* W; __half* O; int C;
    if (s < 20)       { W = W_up; O = Wup;  C = 128; }
    else if (s < 100) { W = W1;   O = W1r;  C = 512; s -= 20; }
    else if (s < 140) { W = W2a;  O = W2ar; C = 256; s -= 100; }
    else              { W = W2b;  O = W2br; C = 256; s -= 140; }
    int o = within >> 5;
    int k = within & 31;
    int cc = s / 5, r = s % 5;
    int kind, c;
    if (r == 0) {
        kind = 0; c = 32 * cc + k;
    } else {
        int base  = (r <= 2) ? 1 : 2;
        int pairc = 32 * cc + ((r == 2 || r == 4) ? 16 : 0);
        if (k < 16) { kind = base;     c = pairc + k; }
        else        { kind = base + 2; c = pairc + k - 16; }
    }
    O[(size_t)s * 8192 + within] = __float2half_rn(W[(o * C + c) * 5 + kind]);
}

// ---------------- merged transpose ----------------
__global__ void trans_both(const float* __restrict__ from_up, const float* __restrict__ from_down,
                           float* __restrict__ U, float* __restrict__ X)
{
    __shared__ float tile[32][33];
    int b  = blockIdx.z;
    int e0 = blockIdx.x * 32;
    const float* in; float* out; int C, os, coff, c0;
    if (blockIdx.y < 4) { in = from_up;   out = U; C = 128; os = 128; coff = 0;   c0 = blockIdx.y * 32; }
    else                { in = from_down; out = X; C = 256; os = 512; coff = 256; c0 = (blockIdx.y - 4) * 32; }
    const float* ip = in + ((size_t)b * C + c0) * E_ + e0;
    #pragma unroll
    for (int i = threadIdx.y; i < 32; i += 8)
        tile[i][threadIdx.x] = ip[(size_t)i * E_ + threadIdx.x];
    __syncthreads();
    float* op = out + ((size_t)(b * E_ + e0)) * os + coff + c0;
    #pragma unroll
    for (int i = threadIdx.y; i < 32; i += 8)
        op[(size_t)i * os + threadIdx.x] = tile[threadIdx.x][i];
}

// ---------------- warp-specialized fused gather + fp16 MMA ----------------
// 384 threads: warps 0-7 = consumers (2x4 grid, 64x64 warp tile, pure LDSM+MMA);
// warps 8-11 = producers (gather + STS A + cp.async B) with REGISTER-PIPELINED
// gathers: LDGs for slab s+1 issue before the STS of slab s, hiding L2 latency
// behind a full iteration of consumer MMA work.
// 4-stage A/B rings. Named barriers: produce-done[st]=1+st, consume-done[st]=5+st,
// count 384. Producer signals slab s-2 after cp.async.wait_group 2.
#define ALD 40                         // row stride in halves
#define A_HALFS (128 * ALD)            // 5120
#define B_HALFS (256 * ALD)            // 10240
#define A_BYTES (A_HALFS * 2)          // 10240
#define B_BYTES (B_HALFS * 2)          // 20480
#define WS_SMEM (4 * A_BYTES + 4 * B_BYTES + 512 * 4 + 512 * 4)   // 126976
#define NTHR 384

template <bool NORM>
__global__ __launch_bounds__(NTHR)
void gconv_ws(const float* __restrict__ Xin, int C,
              const int* __restrict__ ei,
              const __half* __restrict__ Wimg,
              const float* __restrict__ bias,
              float* __restrict__ Yout, int ys,
              float* __restrict__ gsum, float* __restrict__ gssq,
              const float* __restrict__ nmean, const float* __restrict__ nrstd,
              float* __restrict__ zbuf)
{
    extern __shared__ __half smh[];
    __half* smA = smh;                          // 4 stages
    __half* smB = smh + 4 * A_HALFS;            // 4 stages
    int*    snb = (int*)(smh + 4 * A_HALFS + 4 * B_HALFS);   // 512 ints
    float*  nrm = (float*)(snb + 512);                       // 512 floats
    const uint32_t sA_u32 = smem_u32(smA);
    const uint32_t sB_u32 = smem_u32(smB);

    const int tid  = threadIdx.x;
    const int wid  = tid >> 5;
    const int lane = tid & 31;
    const int b  = blockIdx.z;
    const int e0 = blockIdx.x * 128;

    // one-time zero of stats (conv1 only): blocks 0..7 x 1536 floats
    if (zbuf && b == 0 && blockIdx.x < 8)
        *(float4*)&zbuf[blockIdx.x * 1536 + tid * 4] = make_float4(0.f, 0.f, 0.f, 0.f);

    {
        const int* eip = ei + ((size_t)(b * E_) + e0) * 4;
        for (int i = tid; i < 512; i += NTHR)
            snb[i] = (b * E_ + eip[i]) * C;
    }
    if (NORM) {
        for (int i = tid; i < 512; i += NTHR)
            nrm[i] = (i < 256) ? nmean[b * 256 + i] : nrstd[b * 256 + (i - 256)];
    }
    __syncthreads();

    const int x0base = (b * E_ + e0) * C;
    const int slabs  = 5 * (C / 32);

    auto norm4 = [&](float4 v, int cb) -> float4 {
        float4 m4 = *(float4*)&nrm[cb];
        float4 r4 = *(float4*)&nrm[256 + cb];
        v.x = fmaxf((v.x - m4.x) * r4.x, 0.f);
        v.y = fmaxf((v.y - m4.y) * r4.y, 0.f);
        v.z = fmaxf((v.z - m4.z) * r4.z, 0.f);
        v.w = fmaxf((v.w - m4.w) * r4.w, 0.f);
        return v;
    };

    if (wid >= 8) {
        // ======== producers (128 threads), register-pipelined gathers ========
        const int tp = tid - 256;
        float4 rg[2][8];                      // two in-flight slab register sets

        auto issue_gather = [&](int s, int set) {
            int cc = s / 5, r = s % 5;
            if (r == 0) {
                #pragma unroll
                for (int j = 0; j < 8; j++) {
                    int vi = tp + j * 128;
                    int edge = vi >> 3, c4 = (vi & 7) * 4;
                    rg[set][j] = *(const float4*)&Xin[x0base + edge * C + 32 * cc + c4];
                }
            } else {
                int na = (r <= 2) ? 0 : 1;
                int pc = 32 * cc + ((r == 2 || r == 4) ? 16 : 0);
                #pragma unroll
                for (int j = 0; j < 4; j++) {
                    int vi = tp + j * 128;
                    int edge = vi >> 2, c4 = (vi & 3) * 4;
                    int c = pc + c4;
                    rg[set][j]     = *(const float4*)&Xin[snb[edge * 4 + na] + c];
                    rg[set][4 + j] = *(const float4*)&Xin[snb[edge * 4 + na + 2] + c];
                }
            }
        };
        auto sts_slab = [&](int s, int set) {
            int cc = s / 5, r = s % 5;
            __half* A = smA + (s & 3) * A_HALFS;
            if (r == 0) {
                #pragma unroll
                for (int j = 0; j < 8; j++) {
                    int vi = tp + j * 128;
                    int edge = vi >> 3, k = (vi & 7) * 4;
                    float4 a = NORM ? norm4(rg[set][j], 32 * cc + k) : rg[set][j];
                    *(uint2*)&A[edge * ALD + k] = make_uint2(h2u(a.x, a.y), h2u(a.z, a.w));
                }
            } else {
                int pc = 32 * cc + ((r == 2 || r == 4) ? 16 : 0);
                #pragma unroll
                for (int j = 0; j < 4; j++) {
                    int vi = tp + j * 128;
                    int edge = vi >> 2, k = (vi & 3) * 4;
                    float4 pp = rg[set][j], qq = rg[set][4 + j];
                    if (NORM) { pp = norm4(pp, pc + k); qq = norm4(qq, pc + k); }
                    float4 sv = make_float4(pp.x + qq.x, pp.y + qq.y, pp.z + qq.z, pp.w + qq.w);
                    float4 dv = make_float4(fabsf(pp.x - qq.x), fabsf(pp.y - qq.y),
                                            fabsf(pp.z - qq.z), fabsf(pp.w - qq.w));
                    *(uint2*)&A[edge * ALD + k]      = make_uint2(h2u(sv.x, sv.y), h2u(sv.z, sv.w));
                    *(uint2*)&A[edge * ALD + 16 + k] = make_uint2(h2u(dv.x, dv.y), h2u(dv.z, dv.w));
                }
            }
        };

        issue_gather(0, 0);               // slab 0 LDGs in flight
        for (int s = 0; s < slabs; s++) {
            int st = s & 3;
            if (s >= 4) BAR_SYNC_N(5 + st, NTHR);    // stage free?
            // B copy (cp.async)
            {
                const __half* src = Wimg + (size_t)s * 8192;
                uint32_t dstb = sB_u32 + (uint32_t)st * B_BYTES;
                #pragma unroll
                for (int j = 0; j < 8; j++) {
                    int idx = tp + j * 128;
                    int o = idx >> 2, seg = (idx & 3) * 8;
                    CP_ASYNC16(dstb + (uint32_t)(o * ALD + seg) * 2, src + o * 32 + seg);
                }
                CP_COMMIT();
            }
            // issue next slab's gathers BEFORE consuming this slab's registers
            if (s + 1 < slabs) issue_gather(s + 1, (s + 1) & 1);
            // STS this slab (registers issued one iteration ago -> latency hidden)
            sts_slab(s, s & 1);
            if (s >= 2) {
                CP_WAIT2();                              // groups <= s-2 retired
                BAR_ARRIVE_N(1 + ((s - 2) & 3), NTHR);   // slab s-2 ready
            }
        }
        CP_WAIT0();
        BAR_ARRIVE_N(1 + ((slabs - 2) & 3), NTHR);
        BAR_ARRIVE_N(1 + ((slabs - 1) & 3), NTHR);
    } else {
        // =================== consumers (8 warps, 64x64 tiles) ===================
        const int g = lane >> 2;
        const int t = lane & 3;
        const int wm = wid >> 2;     // 0..1: 64-edge half
        const int wn = wid & 3;      // 0..3: 64-out quarter

        float acc[4][8][4];
        #pragma unroll
        for (int mt = 0; mt < 4; mt++)
            #pragma unroll
            for (int nt = 0; nt < 8; nt++)
                #pragma unroll
                for (int rr = 0; rr < 4; rr++) acc[mt][nt][rr] = 0.f;

        for (int s = 0; s < slabs; s++) {
            int st = s & 3;
            BAR_SYNC_N(1 + st, NTHR);                // slab ready
            const uint32_t Abase = sA_u32 + (uint32_t)st * A_BYTES;
            const uint32_t Bbase = sB_u32 + (uint32_t)st * B_BYTES;
            #pragma unroll
            for (int ks = 0; ks < 2; ks++) {
                uint32_t af[4][4];
                #pragma unroll
                for (int mt = 0; mt < 4; mt++) {
                    int row = wm * 64 + mt * 16 + (lane & 15);
                    int kof = ks * 16 + ((lane & 16) ? 8 : 0);
                    LDSM_X4(af[mt][0], af[mt][1], af[mt][2], af[mt][3],
                            Abase + (uint32_t)(row * ALD + kof) * 2);
                }
                #pragma unroll
                for (int np = 0; np < 4; np++) {
                    uint32_t b0, b1, b2, b3;
                    int nrow = wn * 64 + np * 16 + (lane & 7) + ((lane & 16) ? 8 : 0);
                    int kof  = ks * 16 + ((lane & 8) ? 8 : 0);
                    LDSM_X4(b0, b1, b2, b3, Bbase + (uint32_t)(nrow * ALD + kof) * 2);
                    uint32_t bf0[2] = {b0, b1}, bf1[2] = {b2, b3};
                    #pragma unroll
                    for (int mt = 0; mt < 4; mt++) {
                        mma16816(acc[mt][2 * np],     af[mt], bf0);
                        mma16816(acc[mt][2 * np + 1], af[mt], bf1);
                    }
                }
            }
            BAR_ARRIVE_N(5 + st, NTHR);              // stage free
        }

        // ---- epilogue: +bias, float2 stores, optional stats ----
        #pragma unroll
        for (int nt = 0; nt < 8; nt++) {
            int col = wn * 64 + nt * 8 + 2 * t;
            float bv0 = bias[col], bv1 = bias[col + 1];
            float s0 = 0.f, q0 = 0.f, s1 = 0.f, q1 = 0.f;
            #pragma unroll
            for (int mt = 0; mt < 4; mt++) {
                int row = e0 + wm * 64 + mt * 16 + g;
                float a0 = acc[mt][nt][0] + bv0, a1 = acc[mt][nt][1] + bv1;
                float a2 = acc[mt][nt][2] + bv0, a3 = acc[mt][nt][3] + bv1;
                *(float2*)&Yout[((size_t)(b * E_ + row)) * ys + col] = make_float2(a0, a1);
                *(float2*)&Yout[((size_t)(b * E_ + row + 8)) * ys + col] = make_float2(a2, a3);
                s0 += a0 + a2;  q0 += a0 * a0 + a2 * a2;
                s1 += a1 + a3;  q1 += a1 * a1 + a3 * a3;
            }
            if (gsum) {
                #pragma unroll
                for (int m = 16; m >= 4; m >>= 1) {
                    s0 += __shfl_xor_sync(0xffffffffu, s0, m);
                    q0 += __shfl_xor_sync(0xffffffffu, q0, m);
                    s1 += __shfl_xor_sync(0xffffffffu, s1, m);
                    q1 += __shfl_xor_sync(0xffffffffu, q1, m);
                }
                if (g == 0) {
                    atomicAdd(&gsum[b * 256 + col],     s0);
                    atomicAdd(&gsum[b * 256 + col + 1], s1);
                    atomicAdd(&gssq[b * 256 + col],     q0);
                    atomicAdd(&gssq[b * 256 + col + 1], q1);
                }
            }
        }
    }
}

// ---------------- finalize stats ----------------
__global__ void finalize_stats(const float* __restrict__ gsum, const float* __restrict__ gssq,
                               float* __restrict__ mean, float* __restrict__ rstd)
{
    int i = blockIdx.x * blockDim.x + threadIdx.x;
    if (i < B_ * 256) {
        float m = gsum[i] * (1.f / E_);
        float v = gssq[i] * (1.f / E_) - m * m;
        mean[i] = m;
        rstd[i] = rsqrtf(v + 1e-5f);
    }
}

// block-A combine: X2 = relu((Z2-m2)*r2 + relu((Z1-m1)*r1))
__global__ void apply_norm2(const float* __restrict__ Z2, const float* __restrict__ Z1,
                            const float* __restrict__ mean2, const float* __restrict__ rstd2,
                            const float* __restrict__ mean1, const float* __restrict__ rstd1,
                            float* __restrict__ out)
{
    size_t i = (size_t)blockIdx.x * blockDim.x + threadIdx.x;   // float4 index
    int b = (int)(i >> 20);
    int c = ((int)i & 63) * 4;
    float4 z2 = ((const float4*)Z2)[i];
    float4 z1 = ((const float4*)Z1)[i];
    int mi = b * 256 + c;
    float4 o;
    {
        float x1x = fmaxf((z1.x - mean1[mi])     * rstd1[mi],     0.f);
        float x1y = fmaxf((z1.y - mean1[mi + 1]) * rstd1[mi + 1], 0.f);
        float x1z = fmaxf((z1.z - mean1[mi + 2]) * rstd1[mi + 2], 0.f);
        float x1w = fmaxf((z1.w - mean1[mi + 3]) * rstd1[mi + 3], 0.f);
        o.x = fmaxf((z2.x - mean2[mi])     * rstd2[mi]     + x1x, 0.f);
        o.y = fmaxf((z2.y - mean2[mi + 1]) * rstd2[mi + 1] + x1y, 0.f);
        o.z = fmaxf((z2.z - mean2[mi + 2]) * rstd2[mi + 2] + x1z, 0.f);
        o.w = fmaxf((z2.w - mean2[mi + 3]) * rstd2[mi + 3] + x1w, 0.f);
    }
    ((float4*)out)[i] = o;
}

// final: relu((Z-mean)*rstd + res) with transposed store -> [B,256,E]
__global__ void apply_norm_t(const float* __restrict__ Z, const float* __restrict__ res,
                             const float* __restrict__ mean, const float* __restrict__ rstd,
                             float* __restrict__ out)
{
    __shared__ float tile[32][33];
    int b  = blockIdx.z;
    int e0 = blockIdx.x * 32, c0 = blockIdx.y * 32;
    int c  = c0 + threadIdx.x;
    float m = mean[b * 256 + c], r = rstd[b * 256 + c];
    #pragma unroll
    for (int i = threadIdx.y; i < 32; i += 8) {
        size_t idx = ((size_t)(b * E_ + e0 + i)) * 256 + c;
        float v = (Z[idx] - m) * r + res[idx];
        tile[i][threadIdx.x] = fmaxf(v, 0.f);
    }
    __syncthreads();
    float* op = out + ((size_t)(b * 256 + c0)) * E_ + e0;
    #pragma unroll
    for (int i = threadIdx.y; i < 32; i += 8)
        op[(size_t)i * E_ + threadIdx.x] = tile[threadIdx.x][i];
}

// ---------------- host ----------------
extern "C" void kernel_launch(void* const* d_in, const int* in_sizes, int n_in,
                              void* d_out, int out_size)
{
    const float* from_up   = (const float*)d_in[0];
    const float* from_down = (const float*)d_in[1];
    const int*   ei        = (const int*)  d_in[2];
    const float* W_up = (const float*)d_in[3];
    const float* b_up = (const float*)d_in[4];
    const float* W1   = (const float*)d_in[5];
    const float* b1   = (const float*)d_in[6];
    const float* W2a  = (const float*)d_in[7];
    const float* b2a  = (const float*)d_in[8];
    const float* W2b  = (const float*)d_in[9];
    const float* b2b  = (const float*)d_in[10];
    float* out = (float*)d_out;

    float *U, *X, *Z, *Z2, *X2, *stats, *mean1, *rstd1, *mean2, *rstd2;
    __half *Wup, *W1r, *W2ar, *W2br;
    cudaGetSymbolAddress((void**)&U,    g_U);
    cudaGetSymbolAddress((void**)&X,    g_X);
    cudaGetSymbolAddress((void**)&Z,    g_Z);
    cudaGetSymbolAddress((void**)&Z2,   g_Z2);
    cudaGetSymbolAddress((void**)&X2,   g_X2);
    cudaGetSymbolAddress((void**)&Wup,  g_Wup);
    cudaGetSymbolAddress((void**)&W1r,  g_W1r);
    cudaGetSymbolAddress((void**)&W2ar, g_W2ar);
    cudaGetSymbolAddress((void**)&W2br, g_W2br);
    cudaGetSymbolAddress((void**)&stats, g_stats);
    cudaGetSymbolAddress((void**)&mean1, g_mean);
    cudaGetSymbolAddress((void**)&rstd1, g_rstd);
    cudaGetSymbolAddress((void**)&mean2, g_mean2);
    cudaGetSymbolAddress((void**)&rstd2, g_rstd2);

    float* sum1 = stats;           float* ssq1 = stats + 2048;
    float* sum2 = stats + 4096;    float* ssq2 = stats + 6144;
    float* sum3 = stats + 8192;    float* ssq3 = stats + 10240;

    cudaFuncSetAttribute(gconv_ws<false>, cudaFuncAttributeMaxDynamicSharedMemorySize, WS_SMEM);
    cudaFuncSetAttribute(gconv_ws<true>,  cudaFuncAttributeMaxDynamicSharedMemorySize, WS_SMEM);

    // (1) merged weight-image prep
    prep_w_all<<<(180 * 8192) / 256, 256>>>(W_up, W1, W2a, W2b, Wup, W1r, W2ar, W2br);

    // (2) merged input transposes
    trans_both<<<dim3(E_ / 32, 12, B_), dim3(32, 8)>>>(from_up, from_down, U, X);

    dim3 cg(E_ / 128, 1, B_);
    // (3) conv1 -> X cols 0..255; zeroes stats
    gconv_ws<false><<<cg, NTHR, WS_SMEM>>>(U, 128, ei, Wup, b_up, X, 512,
                                           nullptr, nullptr, nullptr, nullptr, stats);

    // (4) conv2 -> Z1, fused stats  [ncu capture slot target]
    gconv_ws<false><<<cg, NTHR, WS_SMEM>>>(X, 512, ei, W1r, b1, Z, 256,
                                           sum1, ssq1, nullptr, nullptr, nullptr);
    finalize_stats<<<(B_ * 256 + 255) / 256, 256>>>(sum1, ssq1, mean1, rstd1);

    // conv3: gathers relu(norm1(Z1)) on the fly -> Z2, fused stats
    gconv_ws<true><<<cg, NTHR, WS_SMEM>>>(Z, 256, ei, W2ar, b2a, Z2, 256,
                                          sum2, ssq2, mean1, rstd1, nullptr);
    finalize_stats<<<(B_ * 256 + 255) / 256, 256>>>(sum2, ssq2, mean2, rstd2);

    // block-A combine: X2 = relu(norm2(Z2) + relu(norm1(Z1)))
    apply_norm2<<<32768, 256>>>(Z2, Z, mean2, rstd2, mean1, rstd1, X2);

    // conv4: X2 -> Z3 (reuse g_Z), fused stats
    gconv_ws<false><<<cg, NTHR, WS_SMEM>>>(X2, 256, ei, W2br, b2b, Z, 256,
                                           sum3, ssq3, nullptr, nullptr, nullptr);
    finalize_stats<<<(B_ * 256 + 255) / 256, 256>>>(sum3, ssq3, mean1, rstd1);

    // final: relu(norm(Z3) + X2), transposed straight to out
    apply_norm_t<<<dim3(E_ / 32, 256 / 32, B_), dim3(32, 8)>>>(Z, X2, mean1, rstd1, out);
}

// round 15
// speedup vs baseline: 1.3024x; 1.3024x over previous
#include <cuda_runtime.h>
#include <cuda_fp16.h>
#include <cuda_bf16.h>
#include <math.h>
#include <stdint.h>

#define B_ 8
#define E_ 16384
#define O_ 256

// ---------------- scratch (__device__ globals; no allocs allowed) ----------------
__device__ float g_U [(size_t)B_*E_*128];   // from_up, edge-major
__device__ float g_X [(size_t)B_*E_*512];   // concat(conv1, from_down), edge-major
__device__ float g_Z [(size_t)B_*E_*256];   // Z1 (conv2 out), later Z3 (conv4 out)
__device__ float g_Z2[(size_t)B_*E_*256];   // Z2 (conv3 out)
__device__ float g_X2[(size_t)B_*E_*256];   // block-A output (residual input for final)
__device__ __half g_Wup [5*128*256];
__device__ __half g_W1r [5*512*256];
__device__ __half g_W2ar[5*256*256];
__device__ __half g_W2br[5*256*256];
// stats: [0]=sum1 [2048]=ssq1 [4096]=sum2 [6144]=ssq2 [8192]=sum3 [10240]=ssq3
__device__ float g_stats[6*2048];
__device__ float g_mean [B_*256];
__device__ float g_rstd [B_*256];
__device__ float g_mean2[B_*256];
__device__ float g_rstd2[B_*256];

__device__ __forceinline__ uint32_t smem_u32(const void* p) {
    uint32_t a;
    asm("{ .reg .u64 t; cvta.to.shared.u64 t, %1; cvt.u32.u64 %0, t; }" : "=r"(a) : "l"(p));
    return a;
}
#define CP_ASYNC16(dst, src) \
    asm volatile("cp.async.cg.shared.global [%0], [%1], 16;" :: "r"(dst), "l"(src))
#define CP_COMMIT() asm volatile("cp.async.commit_group;" ::: "memory")
#define CP_WAIT2()  asm volatile("cp.async.wait_group 2;" ::: "memory")
#define CP_WAIT0()  asm volatile("cp.async.wait_group 0;" ::: "memory")
#define BAR_SYNC_N(id, cnt)   asm volatile("bar.sync %0, %1;"   :: "r"(id), "r"(cnt) : "memory")
#define BAR_ARRIVE_N(id, cnt) asm volatile("bar.arrive %0, %1;" :: "r"(id), "r"(cnt) : "memory")
#define LDSM_X4(r0, r1, r2, r3, addr) \
    asm volatile("ldmatrix.sync.aligned.m8n8.x4.shared.b16 {%0,%1,%2,%3}, [%4];" \
        : "=r"(r0), "=r"(r1), "=r"(r2), "=r"(r3) : "r"(addr))

__device__ __forceinline__ void mma16816(float* d, const uint32_t* a, const uint32_t* b)
{
    asm volatile(
        "mma.sync.aligned.m16n8k16.row.col.f32.f16.f16.f32 "
        "{%0,%1,%2,%3}, {%4,%5,%6,%7}, {%8,%9}, {%0,%1,%2,%3};"
        : "+f"(d[0]), "+f"(d[1]), "+f"(d[2]), "+f"(d[3])
        : "r"(a[0]), "r"(a[1]), "r"(a[2]), "r"(a[3]), "r"(b[0]), "r"(b[1]));
}

__device__ __forceinline__ uint32_t h2u(float x, float y) {
    __half2 h = __floats2half2_rn(x, y);
    return *reinterpret_cast<uint32_t*>(&h);
}

// ---------------- slab map ----------------
// slab s (32 K-rows): cc = s/5, r = s%5
//  r=0: kind0 (center), channels [32cc, +32)
//  r=1: pair(1,3) chunk [32cc, +16)      rows 0-15 = n1+n3, rows 16-31 = |n1-n3|
//  r=2: pair(1,3) chunk [32cc+16, +16)
//  r=3: pair(2,4) chunk [32cc, +16)
//  r=4: pair(2,4) chunk [32cc+16, +16)

// ---------------- merged weight image prep ----------------
__global__ void prep_w_all(const float* __restrict__ W_up, const float* __restrict__ W1,
                           const float* __restrict__ W2a, const float* __restrict__ W2b,
                           __half* __restrict__ Wup, __half* __restrict__ W1r,
                           __half* __restrict__ W2ar, __half* __restrict__ W2br)
{
    int i = blockIdx.x * blockDim.x + threadIdx.x;   // < 180*8192
    int s = i >> 13;
    int within = i & 8191;
    const float* W; __half* O; int C;
    if (s < 20)       { W = W_up; O = Wup;  C = 128; }
    else if (s < 100) { W = W1;   O = W1r;  C = 512; s -= 20; }
    else if (s < 140) { W = W2a;  O = W2ar; C = 256; s -= 100; }
    else              { W = W2b;  O = W2br; C = 256; s -= 140; }
    int o = within >> 5;
    int k = within & 31;
    int cc = s / 5, r = s % 5;
    int kind, c;
    if (r == 0) {
        kind = 0; c = 32 * cc + k;
    } else {
        int base  = (r <= 2) ? 1 : 2;
        int pairc = 32 * cc + ((r == 2 || r == 4) ? 16 : 0);
        if (k < 16) { kind = base;     c = pairc + k; }
        else        { kind = base + 2; c = pairc + k - 16; }
    }
    O[(size_t)s * 8192 + within] = __float2half_rn(W[(o * C + c) * 5 + kind]);
}

// ---------------- merged transpose ----------------
__global__ void trans_both(const float* __restrict__ from_up, const float* __restrict__ from_down,
                           float* __restrict__ U, float* __restrict__ X)
{
    __shared__ float tile[32][33];
    int b  = blockIdx.z;
    int e0 = blockIdx.x * 32;
    const float* in; float* out; int C, os, coff, c0;
    if (blockIdx.y < 4) { in = from_up;   out = U; C = 128; os = 128; coff = 0;   c0 = blockIdx.y * 32; }
    else                { in = from_down; out = X; C = 256; os = 512; coff = 256; c0 = (blockIdx.y - 4) * 32; }
    const float* ip = in + ((size_t)b * C + c0) * E_ + e0;
    #pragma unroll
    for (int i = threadIdx.y; i < 32; i += 8)
        tile[i][threadIdx.x] = ip[(size_t)i * E_ + threadIdx.x];
    __syncthreads();
    float* op = out + ((size_t)(b * E_ + e0)) * os + coff + c0;
    #pragma unroll
    for (int i = threadIdx.y; i < 32; i += 8)
        op[(size_t)i * os + threadIdx.x] = tile[threadIdx.x][i];
}

// ---------------- warp-specialized fused gather + fp16 MMA ----------------
// 384 threads: warps 0-7 = consumers (2x4 grid, 64x64 warp tile, pure LDSM+MMA);
// warps 8-11 = producers with register-pipelined gathers (loop unrolled 2x,
// two STATICALLY-indexed register sets -> no local spills; LDGs for slab s+1
// are in flight one full iteration before their STS).
// 4-stage A/B rings. Named barriers: produce-done[st]=1+st, consume-done[st]=5+st,
// count 384. Producer signals slab s-2 after cp.async.wait_group 2.
#define ALD 40                         // row stride in halves
#define A_HALFS (128 * ALD)            // 5120
#define B_HALFS (256 * ALD)            // 10240
#define A_BYTES (A_HALFS * 2)          // 10240
#define B_BYTES (B_HALFS * 2)          // 20480
#define WS_SMEM (4 * A_BYTES + 4 * B_BYTES + 512 * 4 + 512 * 4)   // 126976
#define NTHR 384

template <bool NORM>
__global__ __launch_bounds__(NTHR)
void gconv_ws(const float* __restrict__ Xin, int C,
              const int* __restrict__ ei,
              const __half* __restrict__ Wimg,
              const float* __restrict__ bias,
              float* __restrict__ Yout, int ys,
              float* __restrict__ gsum, float* __restrict__ gssq,
              const float* __restrict__ nmean, const float* __restrict__ nrstd,
              float* __restrict__ zbuf)
{
    extern __shared__ __half smh[];
    __half* smA = smh;                          // 4 stages
    __half* smB = smh + 4 * A_HALFS;            // 4 stages
    int*    snb = (int*)(smh + 4 * A_HALFS + 4 * B_HALFS);   // 512 ints
    float*  nrm = (float*)(snb + 512);                       // 512 floats
    const uint32_t sA_u32 = smem_u32(smA);
    const uint32_t sB_u32 = smem_u32(smB);

    const int tid  = threadIdx.x;
    const int wid  = tid >> 5;
    const int lane = tid & 31;
    const int b  = blockIdx.z;
    const int e0 = blockIdx.x * 128;

    // one-time zero of stats (conv1 only): blocks 0..7 x 1536 floats
    if (zbuf && b == 0 && blockIdx.x < 8)
        *(float4*)&zbuf[blockIdx.x * 1536 + tid * 4] = make_float4(0.f, 0.f, 0.f, 0.f);

    {
        const int* eip = ei + ((size_t)(b * E_) + e0) * 4;
        for (int i = tid; i < 512; i += NTHR)
            snb[i] = (b * E_ + eip[i]) * C;
    }
    if (NORM) {
        for (int i = tid; i < 512; i += NTHR)
            nrm[i] = (i < 256) ? nmean[b * 256 + i] : nrstd[b * 256 + (i - 256)];
    }
    __syncthreads();

    const int x0base = (b * E_ + e0) * C;
    const int slabs  = 5 * (C / 32);    // always even (20 / 40 / 80)

    auto norm4 = [&](float4 v, int cb) -> float4 {
        float4 m4 = *(float4*)&nrm[cb];
        float4 r4 = *(float4*)&nrm[256 + cb];
        v.x = fmaxf((v.x - m4.x) * r4.x, 0.f);
        v.y = fmaxf((v.y - m4.y) * r4.y, 0.f);
        v.z = fmaxf((v.z - m4.z) * r4.z, 0.f);
        v.w = fmaxf((v.w - m4.w) * r4.w, 0.f);
        return v;
    };

    if (wid >= 8) {
        // ======== producers (128 threads), static register pipeline ========
        const int tp = tid - 256;
        float4 rg0[8], rg1[8];     // two register sets, ALWAYS statically indexed

        auto issue_gather = [&](int s, float4 (&rg)[8]) {
            int cc = s / 5, r = s % 5;
            if (r == 0) {
                #pragma unroll
                for (int j = 0; j < 8; j++) {
                    int vi = tp + j * 128;
                    int edge = vi >> 3, c4 = (vi & 7) * 4;
                    rg[j] = *(const float4*)&Xin[x0base + edge * C + 32 * cc + c4];
                }
            } else {
                int na = (r <= 2) ? 0 : 1;
                int pc = 32 * cc + ((r == 2 || r == 4) ? 16 : 0);
                #pragma unroll
                for (int j = 0; j < 4; j++) {
                    int vi = tp + j * 128;
                    int edge = vi >> 2, c4 = (vi & 3) * 4;
                    int c = pc + c4;
                    rg[j]     = *(const float4*)&Xin[snb[edge * 4 + na] + c];
                    rg[4 + j] = *(const float4*)&Xin[snb[edge * 4 + na + 2] + c];
                }
            }
        };
        auto sts_slab = [&](int s, float4 (&rg)[8]) {
            int cc = s / 5, r = s % 5;
            __half* A = smA + (s & 3) * A_HALFS;
            if (r == 0) {
                #pragma unroll
                for (int j = 0; j < 8; j++) {
                    int vi = tp + j * 128;
                    int edge = vi >> 3, k = (vi & 7) * 4;
                    float4 a = NORM ? norm4(rg[j], 32 * cc + k) : rg[j];
                    *(uint2*)&A[edge * ALD + k] = make_uint2(h2u(a.x, a.y), h2u(a.z, a.w));
                }
            } else {
                int pc = 32 * cc + ((r == 2 || r == 4) ? 16 : 0);
                #pragma unroll
                for (int j = 0; j < 4; j++) {
                    int vi = tp + j * 128;
                    int edge = vi >> 2, k = (vi & 3) * 4;
                    float4 pp = rg[j], qq = rg[4 + j];
                    if (NORM) { pp = norm4(pp, pc + k); qq = norm4(qq, pc + k); }
                    float4 sv = make_float4(pp.x + qq.x, pp.y + qq.y, pp.z + qq.z, pp.w + qq.w);
                    float4 dv = make_float4(fabsf(pp.x - qq.x), fabsf(pp.y - qq.y),
                                            fabsf(pp.z - qq.z), fabsf(pp.w - qq.w));
                    *(uint2*)&A[edge * ALD + k]      = make_uint2(h2u(sv.x, sv.y), h2u(sv.z, sv.w));
                    *(uint2*)&A[edge * ALD + 16 + k] = make_uint2(h2u(dv.x, dv.y), h2u(dv.z, dv.w));
                }
            }
        };
        auto copyB = [&](int s) {
            const __half* src = Wimg + (size_t)s * 8192;
            uint32_t dstb = sB_u32 + (uint32_t)(s & 3) * B_BYTES;
            #pragma unroll
            for (int j = 0; j < 8; j++) {
                int idx = tp + j * 128;
                int o = idx >> 2, seg = (idx & 3) * 8;
                CP_ASYNC16(dstb + (uint32_t)(o * ALD + seg) * 2, src + o * 32 + seg);
            }
            CP_COMMIT();
        };
        auto step = [&](int s, float4 (&cur)[8], float4 (&nxt)[8]) {
            int st = s & 3;
            if (s >= 4) BAR_SYNC_N(5 + st, NTHR);        // stage free?
            copyB(s);
            if (s + 1 < slabs) issue_gather(s + 1, nxt); // LDGs in flight 1 iter early
            sts_slab(s, cur);
            if (s >= 2) {
                CP_WAIT2();                              // groups <= s-2 retired
                BAR_ARRIVE_N(1 + ((s - 2) & 3), NTHR);   // slab s-2 ready
            }
        };

        issue_gather(0, rg0);
        for (int s = 0; s < slabs; s += 2) {
            step(s,     rg0, rg1);
            step(s + 1, rg1, rg0);
        }
        CP_WAIT0();
        BAR_ARRIVE_N(1 + ((slabs - 2) & 3), NTHR);
        BAR_ARRIVE_N(1 + ((slabs - 1) & 3), NTHR);
    } else {
        // =================== consumers (8 warps, 64x64 tiles) ===================
        const int g = lane >> 2;
        const int t = lane & 3;
        const int wm = wid >> 2;     // 0..1: 64-edge half
        const int wn = wid & 3;      // 0..3: 64-out quarter

        float acc[4][8][4];
        #pragma unroll
        for (int mt = 0; mt < 4; mt++)
            #pragma unroll
            for (int nt = 0; nt < 8; nt++)
                #pragma unroll
                for (int rr = 0; rr < 4; rr++) acc[mt][nt][rr] = 0.f;

        for (int s = 0; s < slabs; s++) {
            int st = s & 3;
            BAR_SYNC_N(1 + st, NTHR);                // slab ready
            const uint32_t Abase = sA_u32 + (uint32_t)st * A_BYTES;
            const uint32_t Bbase = sB_u32 + (uint32_t)st * B_BYTES;
            #pragma unroll
            for (int ks = 0; ks < 2; ks++) {
                uint32_t af[4][4];
                #pragma unroll
                for (int mt = 0; mt < 4; mt++) {
                    int row = wm * 64 + mt * 16 + (lane & 15);
                    int kof = ks * 16 + ((lane & 16) ? 8 : 0);
                    LDSM_X4(af[mt][0], af[mt][1], af[mt][2], af[mt][3],
                            Abase + (uint32_t)(row * ALD + kof) * 2);
                }
                #pragma unroll
                for (int np = 0; np < 4; np++) {
                    uint32_t b0, b1, b2, b3;
                    int nrow = wn * 64 + np * 16 + (lane & 7) + ((lane & 16) ? 8 : 0);
                    int kof  = ks * 16 + ((lane & 8) ? 8 : 0);
                    LDSM_X4(b0, b1, b2, b3, Bbase + (uint32_t)(nrow * ALD + kof) * 2);
                    uint32_t bf0[2] = {b0, b1}, bf1[2] = {b2, b3};
                    #pragma unroll
                    for (int mt = 0; mt < 4; mt++) {
                        mma16816(acc[mt][2 * np],     af[mt], bf0);
                        mma16816(acc[mt][2 * np + 1], af[mt], bf1);
                    }
                }
            }
            BAR_ARRIVE_N(5 + st, NTHR);              // stage free
        }

        // ---- epilogue: +bias, float2 stores, optional stats ----
        #pragma unroll
        for (int nt = 0; nt < 8; nt++) {
            int col = wn * 64 + nt * 8 + 2 * t;
            float bv0 = bias[col], bv1 = bias[col + 1];
            float s0 = 0.f, q0 = 0.f, s1 = 0.f, q1 = 0.f;
            #pragma unroll
            for (int mt = 0; mt < 4; mt++) {
                int row = e0 + wm * 64 + mt * 16 + g;
                float a0 = acc[mt][nt][0] + bv0, a1 = acc[mt][nt][1] + bv1;
                float a2 = acc[mt][nt][2] + bv0, a3 = acc[mt][nt][3] + bv1;
                *(float2*)&Yout[((size_t)(b * E_ + row)) * ys + col] = make_float2(a0, a1);
                *(float2*)&Yout[((size_t)(b * E_ + row + 8)) * ys + col] = make_float2(a2, a3);
                s0 += a0 + a2;  q0 += a0 * a0 + a2 * a2;
                s1 += a1 + a3;  q1 += a1 * a1 + a3 * a3;
            }
            if (gsum) {
                #pragma unroll
                for (int m = 16; m >= 4; m >>= 1) {
                    s0 += __shfl_xor_sync(0xffffffffu, s0, m);
                    q0 += __shfl_xor_sync(0xffffffffu, q0, m);
                    s1 += __shfl_xor_sync(0xffffffffu, s1, m);
                    q1 += __shfl_xor_sync(0xffffffffu, q1, m);
                }
                if (g == 0) {
                    atomicAdd(&gsum[b * 256 + col],     s0);
                    atomicAdd(&gsum[b * 256 + col + 1], s1);
                    atomicAdd(&gssq[b * 256 + col],     q0);
                    atomicAdd(&gssq[b * 256 + col + 1], q1);
                }
            }
        }
    }
}

// ---------------- finalize stats ----------------
__global__ void finalize_stats(const float* __restrict__ gsum, const float* __restrict__ gssq,
                               float* __restrict__ mean, float* __restrict__ rstd)
{
    int i = blockIdx.x * blockDim.x + threadIdx.x;
    if (i < B_ * 256) {
        float m = gsum[i] * (1.f / E_);
        float v = gssq[i] * (1.f / E_) - m * m;
        mean[i] = m;
        rstd[i] = rsqrtf(v + 1e-5f);
    }
}

// block-A combine: X2 = relu((Z2-m2)*r2 + relu((Z1-m1)*r1))
__global__ void apply_norm2(const float* __restrict__ Z2, const float* __restrict__ Z1,
                            const float* __restrict__ mean2, const float* __restrict__ rstd2,
                            const float* __restrict__ mean1, const float* __restrict__ rstd1,
                            float* __restrict__ out)
{
    size_t i = (size_t)blockIdx.x * blockDim.x + threadIdx.x;   // float4 index
    int b = (int)(i >> 20);
    int c = ((int)i & 63) * 4;
    float4 z2 = ((const float4*)Z2)[i];
    float4 z1 = ((const float4*)Z1)[i];
    int mi = b * 256 + c;
    float4 o;
    {
        float x1x = fmaxf((z1.x - mean1[mi])     * rstd1[mi],     0.f);
        float x1y = fmaxf((z1.y - mean1[mi + 1]) * rstd1[mi + 1], 0.f);
        float x1z = fmaxf((z1.z - mean1[mi + 2]) * rstd1[mi + 2], 0.f);
        float x1w = fmaxf((z1.w - mean1[mi + 3]) * rstd1[mi + 3], 0.f);
        o.x = fmaxf((z2.x - mean2[mi])     * rstd2[mi]     + x1x, 0.f);
        o.y = fmaxf((z2.y - mean2[mi + 1]) * rstd2[mi + 1] + x1y, 0.f);
        o.z = fmaxf((z2.z - mean2[mi + 2]) * rstd2[mi + 2] + x1z, 0.f);
        o.w = fmaxf((z2.w - mean2[mi + 3]) * rstd2[mi + 3] + x1w, 0.f);
    }
    ((float4*)out)[i] = o;
}

// final: relu((Z-mean)*rstd + res) with transposed store -> [B,256,E]
__global__ void apply_norm_t(const float* __restrict__ Z, const float* __restrict__ res,
                             const float* __restrict__ mean, const float* __restrict__ rstd,
                             float* __restrict__ out)
{
    __shared__ float tile[32][33];
    int b  = blockIdx.z;
    int e0 = blockIdx.x * 32, c0 = blockIdx.y * 32;
    int c  = c0 + threadIdx.x;
    float m = mean[b * 256 + c], r = rstd[b * 256 + c];
    #pragma unroll
    for (int i = threadIdx.y; i < 32; i += 8) {
        size_t idx = ((size_t)(b * E_ + e0 + i)) * 256 + c;
        float v = (Z[idx] - m) * r + res[idx];
        tile[i][threadIdx.x] = fmaxf(v, 0.f);
    }
    __syncthreads();
    float* op = out + ((size_t)(b * 256 + c0)) * E_ + e0;
    #pragma unroll
    for (int i = threadIdx.y; i < 32; i += 8)
        op[(size_t)i * E_ + threadIdx.x] = tile[threadIdx.x][i];
}

// ---------------- host ----------------
extern "C" void kernel_launch(void* const* d_in, const int* in_sizes, int n_in,
                              void* d_out, int out_size)
{
    const float* from_up   = (const float*)d_in[0];
    const float* from_down = (const float*)d_in[1];
    const int*   ei        = (const int*)  d_in[2];
    const float* W_up = (const float*)d_in[3];
    const float* b_up = (const float*)d_in[4];
    const float* W1   = (const float*)d_in[5];
    const float* b1   = (const float*)d_in[6];
    const float* W2a  = (const float*)d_in[7];
    const float* b2a  = (const float*)d_in[8];
    const float* W2b  = (const float*)d_in[9];
    const float* b2b  = (const float*)d_in[10];
    float* out = (float*)d_out;

    float *U, *X, *Z, *Z2, *X2, *stats, *mean1, *rstd1, *mean2, *rstd2;
    __half *Wup, *W1r, *W2ar, *W2br;
    cudaGetSymbolAddress((void**)&U,    g_U);
    cudaGetSymbolAddress((void**)&X,    g_X);
    cudaGetSymbolAddress((void**)&Z,    g_Z);
    cudaGetSymbolAddress((void**)&Z2,   g_Z2);
    cudaGetSymbolAddress((void**)&X2,   g_X2);
    cudaGetSymbolAddress((void**)&Wup,  g_Wup);
    cudaGetSymbolAddress((void**)&W1r,  g_W1r);
    cudaGetSymbolAddress((void**)&W2ar, g_W2ar);
    cudaGetSymbolAddress((void**)&W2br, g_W2br);
    cudaGetSymbolAddress((void**)&stats, g_stats);
    cudaGetSymbolAddress((void**)&mean1, g_mean);
    cudaGetSymbolAddress((void**)&rstd1, g_rstd);
    cudaGetSymbolAddress((void**)&mean2, g_mean2);
    cudaGetSymbolAddress((void**)&rstd2, g_rstd2);

    float* sum1 = stats;           float* ssq1 = stats + 2048;
    float* sum2 = stats + 4096;    float* ssq2 = stats + 6144;
    float* sum3 = stats + 8192;    float* ssq3 = stats + 10240;

    cudaFuncSetAttribute(gconv_ws<false>, cudaFuncAttributeMaxDynamicSharedMemorySize, WS_SMEM);
    cudaFuncSetAttribute(gconv_ws<true>,  cudaFuncAttributeMaxDynamicSharedMemorySize, WS_SMEM);

    // (1) merged weight-image prep
    prep_w_all<<<(180 * 8192) / 256, 256>>>(W_up, W1, W2a, W2b, Wup, W1r, W2ar, W2br);

    // (2) merged input transposes
    trans_both<<<dim3(E_ / 32, 12, B_), dim3(32, 8)>>>(from_up, from_down, U, X);

    dim3 cg(E_ / 128, 1, B_);
    // (3) conv1 -> X cols 0..255; zeroes stats
    gconv_ws<false><<<cg, NTHR, WS_SMEM>>>(U, 128, ei, Wup, b_up, X, 512,
                                           nullptr, nullptr, nullptr, nullptr, stats);

    // (4) conv2 -> Z1, fused stats  [ncu capture slot target]
    gconv_ws<false><<<cg, NTHR, WS_SMEM>>>(X, 512, ei, W1r, b1, Z, 256,
                                           sum1, ssq1, nullptr, nullptr, nullptr);
    finalize_stats<<<(B_ * 256 + 255) / 256, 256>>>(sum1, ssq1, mean1, rstd1);

    // conv3: gathers relu(norm1(Z1)) on the fly -> Z2, fused stats
    gconv_ws<true><<<cg, NTHR, WS_SMEM>>>(Z, 256, ei, W2ar, b2a, Z2, 256,
                                          sum2, ssq2, mean1, rstd1, nullptr);
    finalize_stats<<<(B_ * 256 + 255) / 256, 256>>>(sum2, ssq2, mean2, rstd2);

    // block-A combine: X2 = relu(norm2(Z2) + relu(norm1(Z1)))
    apply_norm2<<<32768, 256>>>(Z2, Z, mean2, rstd2, mean1, rstd1, X2);

    // conv4: X2 -> Z3 (reuse g_Z), fused stats
    gconv_ws<false><<<cg, NTHR, WS_SMEM>>>(X2, 256, ei, W2br, b2b, Z, 256,
                                           sum3, ssq3, nullptr, nullptr, nullptr);
    finalize_stats<<<(B_ * 256 + 255) / 256, 256>>>(sum3, ssq3, mean1, rstd1);

    // final: relu(norm(Z3) + X2), transposed straight to out
    apply_norm_t<<<dim3(E_ / 32, 256 / 32, B_), dim3(32, 8)>>>(Z, X2, mean1, rstd1, out);
}

// round 16
// speedup vs baseline: 1.3656x; 1.0485x over previous
#include <cuda_runtime.h>
#include <cuda_fp16.h>
#include <cuda_bf16.h>
#include <math.h>
#include <stdint.h>

#define B_ 8
#define E_ 16384
#define O_ 256

// ---------------- scratch (__device__ globals; no allocs allowed) ----------------
__device__ float g_U [(size_t)B_*E_*128];   // from_up, edge-major
__device__ float g_X [(size_t)B_*E_*512];   // concat(conv1, from_down), edge-major
__device__ float g_Z [(size_t)B_*E_*256];   // Z1 (conv2 out), later Z3 (conv4 out)
__device__ float g_Z2[(size_t)B_*E_*256];   // Z2 (conv3 out)
__device__ float g_X2[(size_t)B_*E_*256];   // block-A output (residual input for final)
__device__ __half g_Wup [5*128*256];
__device__ __half g_W1r [5*512*256];
__device__ __half g_W2ar[5*256*256];
__device__ __half g_W2br[5*256*256];
// stats: [0]=sum1 [2048]=ssq1 [4096]=sum2 [6144]=ssq2 [8192]=sum3 [10240]=ssq3
__device__ float g_stats[6*2048];
__device__ float g_mean [B_*256];
__device__ float g_rstd [B_*256];
__device__ float g_mean2[B_*256];
__device__ float g_rstd2[B_*256];

__device__ __forceinline__ uint32_t smem_u32(const void* p) {
    uint32_t a;
    asm("{ .reg .u64 t; cvta.to.shared.u64 t, %1; cvt.u32.u64 %0, t; }" : "=r"(a) : "l"(p));
    return a;
}
#define CP_ASYNC16(dst, src) \
    asm volatile("cp.async.cg.shared.global [%0], [%1], 16;" :: "r"(dst), "l"(src))
#define CP_COMMIT() asm volatile("cp.async.commit_group;" ::: "memory")
#define CP_WAIT1()  asm volatile("cp.async.wait_group 1;" ::: "memory")
#define CP_WAIT0()  asm volatile("cp.async.wait_group 0;" ::: "memory")
#define BAR_SYNC_N(id, cnt)   asm volatile("bar.sync %0, %1;"   :: "r"(id), "r"(cnt) : "memory")
#define BAR_ARRIVE_N(id, cnt) asm volatile("bar.arrive %0, %1;" :: "r"(id), "r"(cnt) : "memory")
#define LDSM_X4(r0, r1, r2, r3, addr) \
    asm volatile("ldmatrix.sync.aligned.m8n8.x4.shared.b16 {%0,%1,%2,%3}, [%4];" \
        : "=r"(r0), "=r"(r1), "=r"(r2), "=r"(r3) : "r"(addr))

__device__ __forceinline__ void mma16816(float* d, const uint32_t* a, const uint32_t* b)
{
    asm volatile(
        "mma.sync.aligned.m16n8k16.row.col.f32.f16.f16.f32 "
        "{%0,%1,%2,%3}, {%4,%5,%6,%7}, {%8,%9}, {%0,%1,%2,%3};"
        : "+f"(d[0]), "+f"(d[1]), "+f"(d[2]), "+f"(d[3])
        : "r"(a[0]), "r"(a[1]), "r"(a[2]), "r"(a[3]), "r"(b[0]), "r"(b[1]));
}

__device__ __forceinline__ uint32_t h2u(float x, float y) {
    __half2 h = __floats2half2_rn(x, y);
    return *reinterpret_cast<uint32_t*>(&h);
}

// ---------------- slab map ----------------
// slab s (32 K-rows): cc = s/5, r = s%5
//  r=0: kind0 (center), channels [32cc, +32)
//  r=1: pair(1,3) chunk [32cc, +16)      rows 0-15 = n1+n3, rows 16-31 = |n1-n3|
//  r=2: pair(1,3) chunk [32cc+16, +16)
//  r=3: pair(2,4) chunk [32cc, +16)
//  r=4: pair(2,4) chunk [32cc+16, +16)

// ---------------- merged weight image prep ----------------
__global__ void prep_w_all(const float* __restrict__ W_up, const float* __restrict__ W1,
                           const float* __restrict__ W2a, const float* __restrict__ W2b,
                           __half* __restrict__ Wup, __half* __restrict__ W1r,
                           __half* __restrict__ W2ar, __half* __restrict__ W2br)
{
    int i = blockIdx.x * blockDim.x + threadIdx.x;   // < 180*8192
    int s = i >> 13;
    int within = i & 8191;
    const float* W; __half* O; int C;
    if (s < 20)       { W = W_up; O = Wup;  C = 128; }
    else if (s < 100) { W = W1;   O = W1r;  C = 512; s -= 20; }
    else if (s < 140) { W = W2a;  O = W2ar; C = 256; s -= 100; }
    else              { W = W2b;  O = W2br; C = 256; s -= 140; }
    int o = within >> 5;
    int k = within & 31;
    int cc = s / 5, r = s % 5;
    int kind, c;
    if (r == 0) {
        kind = 0; c = 32 * cc + k;
    } else {
        int base  = (r <= 2) ? 1 : 2;
        int pairc = 32 * cc + ((r == 2 || r == 4) ? 16 : 0);
        if (k < 16) { kind = base;     c = pairc + k; }
        else        { kind = base + 2; c = pairc + k - 16; }
    }
    O[(size_t)s * 8192 + within] = __float2half_rn(W[(o * C + c) * 5 + kind]);
}

// ---------------- merged transpose ----------------
__global__ void trans_both(const float* __restrict__ from_up, const float* __restrict__ from_down,
                           float* __restrict__ U, float* __restrict__ X)
{
    __shared__ float tile[32][33];
    int b  = blockIdx.z;
    int e0 = blockIdx.x * 32;
    const float* in; float* out; int C, os, coff, c0;
    if (blockIdx.y < 4) { in = from_up;   out = U; C = 128; os = 128; coff = 0;   c0 = blockIdx.y * 32; }
    else                { in = from_down; out = X; C = 256; os = 512; coff = 256; c0 = (blockIdx.y - 4) * 32; }
    const float* ip = in + ((size_t)b * C + c0) * E_ + e0;
    #pragma unroll
    for (int i = threadIdx.y; i < 32; i += 8)
        tile[i][threadIdx.x] = ip[(size_t)i * E_ + threadIdx.x];
    __syncthreads();
    float* op = out + ((size_t)(b * E_ + e0)) * os + coff + c0;
    #pragma unroll
    for (int i = threadIdx.y; i < 32; i += 8)
        op[(size_t)i * os + threadIdx.x] = tile[threadIdx.x][i];
}

// ---------------- warp-specialized fused gather + fp16 MMA ----------------
// 384 threads: warps 0-7 = consumers (2x4 grid, 64x64 warp tile, pure LDSM+MMA);
// warps 8-11 = producers, register-pipelined gathers (two static reg sets).
// EARLY-SIGNAL protocol: at TOP of producer iter s: cp.async.wait_group 1
// (retires groups <= s-2) then arrive produce-done[s-2] BEFORE doing iter-s
// work. Retirement semantics identical to the late-signal version; the A data
// of slab s-2 was STS'd at iter s-2. Consumers get slabs ~1 producer-iteration
// earlier.
#define ALD 40                         // row stride in halves
#define A_HALFS (128 * ALD)            // 5120
#define B_HALFS (256 * ALD)            // 10240
#define A_BYTES (A_HALFS * 2)          // 10240
#define B_BYTES (B_HALFS * 2)          // 20480
#define WS_SMEM (4 * A_BYTES + 4 * B_BYTES + 512 * 4 + 512 * 4)   // 126976
#define NTHR 384

template <bool NORM>
__global__ __launch_bounds__(NTHR)
void gconv_ws(const float* __restrict__ Xin, int C,
              const int* __restrict__ ei,
              const __half* __restrict__ Wimg,
              const float* __restrict__ bias,
              float* __restrict__ Yout, int ys,
              float* __restrict__ gsum, float* __restrict__ gssq,
              const float* __restrict__ nmean, const float* __restrict__ nrstd,
              float* __restrict__ zbuf)
{
    extern __shared__ __half smh[];
    __half* smA = smh;                          // 4 stages
    __half* smB = smh + 4 * A_HALFS;            // 4 stages
    int*    snb = (int*)(smh + 4 * A_HALFS + 4 * B_HALFS);   // 512 ints
    float*  nrm = (float*)(snb + 512);                       // 512 floats
    const uint32_t sA_u32 = smem_u32(smA);
    const uint32_t sB_u32 = smem_u32(smB);

    const int tid  = threadIdx.x;
    const int wid  = tid >> 5;
    const int lane = tid & 31;
    const int b  = blockIdx.z;
    const int e0 = blockIdx.x * 128;

    // one-time zero of stats (conv1 only): blocks 0..7 x 1536 floats
    if (zbuf && b == 0 && blockIdx.x < 8)
        *(float4*)&zbuf[blockIdx.x * 1536 + tid * 4] = make_float4(0.f, 0.f, 0.f, 0.f);

    {
        const int* eip = ei + ((size_t)(b * E_) + e0) * 4;
        for (int i = tid; i < 512; i += NTHR)
            snb[i] = (b * E_ + eip[i]) * C;
    }
    if (NORM) {
        for (int i = tid; i < 512; i += NTHR)
            nrm[i] = (i < 256) ? nmean[b * 256 + i] : nrstd[b * 256 + (i - 256)];
    }
    __syncthreads();

    const int x0base = (b * E_ + e0) * C;
    const int slabs  = 5 * (C / 32);    // always even (20 / 40 / 80)

    auto norm4 = [&](float4 v, int cb) -> float4 {
        float4 m4 = *(float4*)&nrm[cb];
        float4 r4 = *(float4*)&nrm[256 + cb];
        v.x = fmaxf((v.x - m4.x) * r4.x, 0.f);
        v.y = fmaxf((v.y - m4.y) * r4.y, 0.f);
        v.z = fmaxf((v.z - m4.z) * r4.z, 0.f);
        v.w = fmaxf((v.w - m4.w) * r4.w, 0.f);
        return v;
    };

    if (wid >= 8) {
        // ======== producers (128 threads), static register pipeline ========
        const int tp = tid - 256;
        float4 rg0[8], rg1[8];     // two register sets, ALWAYS statically indexed

        auto issue_gather = [&](int s, float4 (&rg)[8]) {
            int cc = s / 5, r = s % 5;
            if (r == 0) {
                #pragma unroll
                for (int j = 0; j < 8; j++) {
                    int vi = tp + j * 128;
                    int edge = vi >> 3, c4 = (vi & 7) * 4;
                    rg[j] = *(const float4*)&Xin[x0base + edge * C + 32 * cc + c4];
                }
            } else {
                int na = (r <= 2) ? 0 : 1;
                int pc = 32 * cc + ((r == 2 || r == 4) ? 16 : 0);
                #pragma unroll
                for (int j = 0; j < 4; j++) {
                    int vi = tp + j * 128;
                    int edge = vi >> 2, c4 = (vi & 3) * 4;
                    int c = pc + c4;
                    rg[j]     = *(const float4*)&Xin[snb[edge * 4 + na] + c];
                    rg[4 + j] = *(const float4*)&Xin[snb[edge * 4 + na + 2] + c];
                }
            }
        };
        auto sts_slab = [&](int s, float4 (&rg)[8]) {
            int cc = s / 5, r = s % 5;
            __half* A = smA + (s & 3) * A_HALFS;
            if (r == 0) {
                #pragma unroll
                for (int j = 0; j < 8; j++) {
                    int vi = tp + j * 128;
                    int edge = vi >> 3, k = (vi & 7) * 4;
                    float4 a = NORM ? norm4(rg[j], 32 * cc + k) : rg[j];
                    *(uint2*)&A[edge * ALD + k] = make_uint2(h2u(a.x, a.y), h2u(a.z, a.w));
                }
            } else {
                int pc = 32 * cc + ((r == 2 || r == 4) ? 16 : 0);
                #pragma unroll
                for (int j = 0; j < 4; j++) {
                    int vi = tp + j * 128;
                    int edge = vi >> 2, k = (vi & 3) * 4;
                    float4 pp = rg[j], qq = rg[4 + j];
                    if (NORM) { pp = norm4(pp, pc + k); qq = norm4(qq, pc + k); }
                    float4 sv = make_float4(pp.x + qq.x, pp.y + qq.y, pp.z + qq.z, pp.w + qq.w);
                    float4 dv = make_float4(fabsf(pp.x - qq.x), fabsf(pp.y - qq.y),
                                            fabsf(pp.z - qq.z), fabsf(pp.w - qq.w));
                    *(uint2*)&A[edge * ALD + k]      = make_uint2(h2u(sv.x, sv.y), h2u(sv.z, sv.w));
                    *(uint2*)&A[edge * ALD + 16 + k] = make_uint2(h2u(dv.x, dv.y), h2u(dv.z, dv.w));
                }
            }
        };
        auto copyB = [&](int s) {
            const __half* src = Wimg + (size_t)s * 8192;
            uint32_t dstb = sB_u32 + (uint32_t)(s & 3) * B_BYTES;
            #pragma unroll
            for (int j = 0; j < 8; j++) {
                int idx = tp + j * 128;
                int o = idx >> 2, seg = (idx & 3) * 8;
                CP_ASYNC16(dstb + (uint32_t)(o * ALD + seg) * 2, src + o * 32 + seg);
            }
            CP_COMMIT();
        };
        auto step = [&](int s, float4 (&cur)[8], float4 (&nxt)[8]) {
            // EARLY SIGNAL: slab s-2's B retired (wait_group 1: committed = s,
            // keeps only group s-1 pending) and its A was STS'd at iter s-2.
            if (s >= 2) {
                CP_WAIT1();
                BAR_ARRIVE_N(1 + ((s - 2) & 3), NTHR);
            }
            if (s >= 4) BAR_SYNC_N(5 + (s & 3), NTHR);   // stage free?
            copyB(s);
            if (s + 1 < slabs) issue_gather(s + 1, nxt); // LDGs in flight 1 iter early
            sts_slab(s, cur);
        };

        issue_gather(0, rg0);
        for (int s = 0; s < slabs; s += 2) {
            step(s,     rg0, rg1);
            step(s + 1, rg1, rg0);
        }
        CP_WAIT0();
        BAR_ARRIVE_N(1 + ((slabs - 2) & 3), NTHR);
        BAR_ARRIVE_N(1 + ((slabs - 1) & 3), NTHR);
    } else {
        // =================== consumers (8 warps, 64x64 tiles) ===================
        const int g = lane >> 2;
        const int t = lane & 3;
        const int wm = wid >> 2;     // 0..1: 64-edge half
        const int wn = wid & 3;      // 0..3: 64-out quarter

        float acc[4][8][4];
        #pragma unroll
        for (int mt = 0; mt < 4; mt++)
            #pragma unroll
            for (int nt = 0; nt < 8; nt++)
                #pragma unroll
                for (int rr = 0; rr < 4; rr++) acc[mt][nt][rr] = 0.f;

        for (int s = 0; s < slabs; s++) {
            int st = s & 3;
            BAR_SYNC_N(1 + st, NTHR);                // slab ready
            const uint32_t Abase = sA_u32 + (uint32_t)st * A_BYTES;
            const uint32_t Bbase = sB_u32 + (uint32_t)st * B_BYTES;
            #pragma unroll
            for (int ks = 0; ks < 2; ks++) {
                uint32_t af[4][4];
                #pragma unroll
                for (int mt = 0; mt < 4; mt++) {
                    int row = wm * 64 + mt * 16 + (lane & 15);
                    int kof = ks * 16 + ((lane & 16) ? 8 : 0);
                    LDSM_X4(af[mt][0], af[mt][1], af[mt][2], af[mt][3],
                            Abase + (uint32_t)(row * ALD + kof) * 2);
                }
                #pragma unroll
                for (int np = 0; np < 4; np++) {
                    uint32_t b0, b1, b2, b3;
                    int nrow = wn * 64 + np * 16 + (lane & 7) + ((lane & 16) ? 8 : 0);
                    int kof  = ks * 16 + ((lane & 8) ? 8 : 0);
                    LDSM_X4(b0, b1, b2, b3, Bbase + (uint32_t)(nrow * ALD + kof) * 2);
                    uint32_t bf0[2] = {b0, b1}, bf1[2] = {b2, b3};
                    #pragma unroll
                    for (int mt = 0; mt < 4; mt++) {
                        mma16816(acc[mt][2 * np],     af[mt], bf0);
                        mma16816(acc[mt][2 * np + 1], af[mt], bf1);
                    }
                }
            }
            BAR_ARRIVE_N(5 + st, NTHR);              // stage free
        }

        // ---- epilogue: +bias, float2 stores, optional stats ----
        #pragma unroll
        for (int nt = 0; nt < 8; nt++) {
            int col = wn * 64 + nt * 8 + 2 * t;
            float bv0 = bias[col], bv1 = bias[col + 1];
            float s0 = 0.f, q0 = 0.f, s1 = 0.f, q1 = 0.f;
            #pragma unroll
            for (int mt = 0; mt < 4; mt++) {
                int row = e0 + wm * 64 + mt * 16 + g;
                float a0 = acc[mt][nt][0] + bv0, a1 = acc[mt][nt][1] + bv1;
                float a2 = acc[mt][nt][2] + bv0, a3 = acc[mt][nt][3] + bv1;
                *(float2*)&Yout[((size_t)(b * E_ + row)) * ys + col] = make_float2(a0, a1);
                *(float2*)&Yout[((size_t)(b * E_ + row + 8)) * ys + col] = make_float2(a2, a3);
                s0 += a0 + a2;  q0 += a0 * a0 + a2 * a2;
                s1 += a1 + a3;  q1 += a1 * a1 + a3 * a3;
            }
            if (gsum) {
                #pragma unroll
                for (int m = 16; m >= 4; m >>= 1) {
                    s0 += __shfl_xor_sync(0xffffffffu, s0, m);
                    q0 += __shfl_xor_sync(0xffffffffu, q0, m);
                    s1 += __shfl_xor_sync(0xffffffffu, s1, m);
                    q1 += __shfl_xor_sync(0xffffffffu, q1, m);
                }
                if (g == 0) {
                    atomicAdd(&gsum[b * 256 + col],     s0);
                    atomicAdd(&gsum[b * 256 + col + 1], s1);
                    atomicAdd(&gssq[b * 256 + col],     q0);
                    atomicAdd(&gssq[b * 256 + col + 1], q1);
                }
            }
        }
    }
}

// ---------------- finalize stats ----------------
__global__ void finalize_stats(const float* __restrict__ gsum, const float* __restrict__ gssq,
                               float* __restrict__ mean, float* __restrict__ rstd)
{
    int i = blockIdx.x * blockDim.x + threadIdx.x;
    if (i < B_ * 256) {
        float m = gsum[i] * (1.f / E_);
        float v = gssq[i] * (1.f / E_) - m * m;
        mean[i] = m;
        rstd[i] = rsqrtf(v + 1e-5f);
    }
}

// block-A combine: X2 = relu((Z2-m2)*r2 + relu((Z1-m1)*r1))
__global__ void apply_norm2(const float* __restrict__ Z2, const float* __restrict__ Z1,
                            const float* __restrict__ mean2, const float* __restrict__ rstd2,
                            const float* __restrict__ mean1, const float* __restrict__ rstd1,
                            float* __restrict__ out)
{
    size_t i = (size_t)blockIdx.x * blockDim.x + threadIdx.x;   // float4 index
    int b = (int)(i >> 20);
    int c = ((int)i & 63) * 4;
    float4 z2 = ((const float4*)Z2)[i];
    float4 z1 = ((const float4*)Z1)[i];
    int mi = b * 256 + c;
    float4 o;
    {
        float x1x = fmaxf((z1.x - mean1[mi])     * rstd1[mi],     0.f);
        float x1y = fmaxf((z1.y - mean1[mi + 1]) * rstd1[mi + 1], 0.f);
        float x1z = fmaxf((z1.z - mean1[mi + 2]) * rstd1[mi + 2], 0.f);
        float x1w = fmaxf((z1.w - mean1[mi + 3]) * rstd1[mi + 3], 0.f);
        o.x = fmaxf((z2.x - mean2[mi])     * rstd2[mi]     + x1x, 0.f);
        o.y = fmaxf((z2.y - mean2[mi + 1]) * rstd2[mi + 1] + x1y, 0.f);
        o.z = fmaxf((z2.z - mean2[mi + 2]) * rstd2[mi + 2] + x1z, 0.f);
        o.w = fmaxf((z2.w - mean2[mi + 3]) * rstd2[mi + 3] + x1w, 0.f);
    }
    ((float4*)out)[i] = o;
}

// final: relu((Z-mean)*rstd + res) with transposed store -> [B,256,E]
__global__ void apply_norm_t(const float* __restrict__ Z, const float* __restrict__ res,
                             const float* __restrict__ mean, const float* __restrict__ rstd,
                             float* __restrict__ out)
{
    __shared__ float tile[32][33];
    int b  = blockIdx.z;
    int e0 = blockIdx.x * 32, c0 = blockIdx.y * 32;
    int c  = c0 + threadIdx.x;
    float m = mean[b * 256 + c], r = rstd[b * 256 + c];
    #pragma unroll
    for (int i = threadIdx.y; i < 32; i += 8) {
        size_t idx = ((size_t)(b * E_ + e0 + i)) * 256 + c;
        float v = (Z[idx] - m) * r + res[idx];
        tile[i][threadIdx.x] = fmaxf(v, 0.f);
    }
    __syncthreads();
    float* op = out + ((size_t)(b * 256 + c0)) * E_ + e0;
    #pragma unroll
    for (int i = threadIdx.y; i < 32; i += 8)
        op[(size_t)i * E_ + threadIdx.x] = tile[threadIdx.x][i];
}

// ---------------- host ----------------
extern "C" void kernel_launch(void* const* d_in, const int* in_sizes, int n_in,
                              void* d_out, int out_size)
{
    const float* from_up   = (const float*)d_in[0];
    const float* from_down = (const float*)d_in[1];
    const int*   ei        = (const int*)  d_in[2];
    const float* W_up = (const float*)d_in[3];
    const float* b_up = (const float*)d_in[4];
    const float* W1   = (const float*)d_in[5];
    const float* b1   = (const float*)d_in[6];
    const float* W2a  = (const float*)d_in[7];
    const float* b2a  = (const float*)d_in[8];
    const float* W2b  = (const float*)d_in[9];
    const float* b2b  = (const float*)d_in[10];
    float* out = (float*)d_out;

    float *U, *X, *Z, *Z2, *X2, *stats, *mean1, *rstd1, *mean2, *rstd2;
    __half *Wup, *W1r, *W2ar, *W2br;
    cudaGetSymbolAddress((void**)&U,    g_U);
    cudaGetSymbolAddress((void**)&X,    g_X);
    cudaGetSymbolAddress((void**)&Z,    g_Z);
    cudaGetSymbolAddress((void**)&Z2,   g_Z2);
    cudaGetSymbolAddress((void**)&X2,   g_X2);
    cudaGetSymbolAddress((void**)&Wup,  g_Wup);
    cudaGetSymbolAddress((void**)&W1r,  g_W1r);
    cudaGetSymbolAddress((void**)&W2ar, g_W2ar);
    cudaGetSymbolAddress((void**)&W2br, g_W2br);
    cudaGetSymbolAddress((void**)&stats, g_stats);
    cudaGetSymbolAddress((void**)&mean1, g_mean);
    cudaGetSymbolAddress((void**)&rstd1, g_rstd);
    cudaGetSymbolAddress((void**)&mean2, g_mean2);
    cudaGetSymbolAddress((void**)&rstd2, g_rstd2);

    float* sum1 = stats;           float* ssq1 = stats + 2048;
    float* sum2 = stats + 4096;    float* ssq2 = stats + 6144;
    float* sum3 = stats + 8192;    float* ssq3 = stats + 10240;

    cudaFuncSetAttribute(gconv_ws<false>, cudaFuncAttributeMaxDynamicSharedMemorySize, WS_SMEM);
    cudaFuncSetAttribute(gconv_ws<true>,  cudaFuncAttributeMaxDynamicSharedMemorySize, WS_SMEM);

    // (1) merged weight-image prep
    prep_w_all<<<(180 * 8192) / 256, 256>>>(W_up, W1, W2a, W2b, Wup, W1r, W2ar, W2br);

    // (2) merged input transposes
    trans_both<<<dim3(E_ / 32, 12, B_), dim3(32, 8)>>>(from_up, from_down, U, X);

    dim3 cg(E_ / 128, 1, B_);
    // (3) conv1 -> X cols 0..255; zeroes stats
    gconv_ws<false><<<cg, NTHR, WS_SMEM>>>(U, 128, ei, Wup, b_up, X, 512,
                                           nullptr, nullptr, nullptr, nullptr, stats);

    // (4) conv2 -> Z1, fused stats  [ncu capture slot target]
    gconv_ws<false><<<cg, NTHR, WS_SMEM>>>(X, 512, ei, W1r, b1, Z, 256,
                                           sum1, ssq1, nullptr, nullptr, nullptr);
    finalize_stats<<<(B_ * 256 + 255) / 256, 256>>>(sum1, ssq1, mean1, rstd1);

    // conv3: gathers relu(norm1(Z1)) on the fly -> Z2, fused stats
    gconv_ws<true><<<cg, NTHR, WS_SMEM>>>(Z, 256, ei, W2ar, b2a, Z2, 256,
                                          sum2, ssq2, mean1, rstd1, nullptr);
    finalize_stats<<<(B_ * 256 + 255) / 256, 256>>>(sum2, ssq2, mean2, rstd2);

    // block-A combine: X2 = relu(norm2(Z2) + relu(norm1(Z1)))
    apply_norm2<<<32768, 256>>>(Z2, Z, mean2, rstd2, mean1, rstd1, X2);

    // conv4: X2 -> Z3 (reuse g_Z), fused stats
    gconv_ws<false><<<cg, NTHR, WS_SMEM>>>(X2, 256, ei, W2br, b2b, Z, 256,
                                           sum3, ssq3, nullptr, nullptr, nullptr);
    finalize_stats<<<(B_ * 256 + 255) / 256, 256>>>(sum3, ssq3, mean1, rstd1);

    // final: relu(norm(Z3) + X2), transposed straight to out
    apply_norm_t<<<dim3(E_ / 32, 256 / 32, B_), dim3(32, 8)>>>(Z, X2, mean1, rstd1, out);
}